// round 1
// baseline (speedup 1.0000x reference)
#include <cuda_runtime.h>
#include <cuda_bf16.h>

#define NPTS 32768
#define NCH  64     // C == O == 64
#define KNB  16

// Scratch for post-BN/ReLU transformed features, layout [b][n][o] (o contiguous).
// 2 * 32768 * 64 floats = 16.8 MB  (fits in 126 MB L2)
__device__ float g_R[2 * NPTS * NCH];

// ---------------------------------------------------------------------------
// Stage 1: R[b][n][o] = relu( sum_c W[o][c]*inv[o] * feat[b][c][n] + bias[o] )
//   inv[o]  = gamma[o] / sqrt(var[o]+eps)
//   bias[o] = beta[o] - mean[o]*inv[o]
// Block: 256 threads, tile = 64 o x 64 n. Micro-tile 4o x 4n per thread.
// ---------------------------------------------------------------------------
__global__ __launch_bounds__(256) void spe_stage1(
    const float* __restrict__ feat,
    const float* __restrict__ W,
    const float* __restrict__ gamma,
    const float* __restrict__ beta,
    const float* __restrict__ rmean,
    const float* __restrict__ rvar)
{
    __shared__ float sWt[64][64];   // [c][o], pre-scaled by inv[o]
    __shared__ float sBias[64];
    __shared__ float sF[64][64];    // [c][n_local]

    const int b   = blockIdx.y;
    const int n0  = blockIdx.x * 64;
    const int tid = threadIdx.x;

    // Build scaled weight matrix (transposed: c-major rows, o contiguous)
    #pragma unroll
    for (int e = tid; e < 64 * 64; e += 256) {
        int o = e & 63, c = e >> 6;
        float inv = gamma[o] * rsqrtf(rvar[o] + 1e-5f);
        sWt[c][o] = W[o * 64 + c] * inv;
    }
    if (tid < 64) {
        float inv = gamma[tid] * rsqrtf(rvar[tid] + 1e-5f);
        sBias[tid] = beta[tid] - rmean[tid] * inv;
    }

    // Stage feature tile [64 c][64 n] (coalesced float4 along n)
    #pragma unroll
    for (int it = 0; it < 4; it++) {
        int idx = it * 256 + tid;
        int c = idx >> 4, v = idx & 15;
        *(float4*)&sF[c][v * 4] =
            *(const float4*)&feat[((size_t)b * 64 + c) * NPTS + n0 + v * 4];
    }
    __syncthreads();

    const int to = tid & 15;   // o-group: o = to*4 .. to*4+3
    const int tn = tid >> 4;   // n-group: n = tn*4 .. tn*4+3

    float a00=0,a01=0,a02=0,a03=0;
    float a10=0,a11=0,a12=0,a13=0;
    float a20=0,a21=0,a22=0,a23=0;
    float a30=0,a31=0,a32=0,a33=0;

    #pragma unroll 16
    for (int c = 0; c < 64; c++) {
        float4 w = *(float4*)&sWt[c][to * 4];
        float4 f = *(float4*)&sF[c][tn * 4];
        a00 += w.x*f.x; a01 += w.x*f.y; a02 += w.x*f.z; a03 += w.x*f.w;
        a10 += w.y*f.x; a11 += w.y*f.y; a12 += w.y*f.z; a13 += w.y*f.w;
        a20 += w.z*f.x; a21 += w.z*f.y; a22 += w.z*f.z; a23 += w.z*f.w;
        a30 += w.w*f.x; a31 += w.w*f.y; a32 += w.w*f.z; a33 += w.w*f.w;
    }

    float b0 = sBias[to * 4 + 0];
    float b1 = sBias[to * 4 + 1];
    float b2 = sBias[to * 4 + 2];
    float b3 = sBias[to * 4 + 3];

    float acc[4][4] = {{a00,a10,a20,a30},{a01,a11,a21,a31},
                       {a02,a12,a22,a32},{a03,a13,a23,a33}};
    #pragma unroll
    for (int j = 0; j < 4; j++) {
        int n = n0 + tn * 4 + j;
        float4 r;
        r.x = fmaxf(acc[j][0] + b0, 0.f);
        r.y = fmaxf(acc[j][1] + b1, 0.f);
        r.z = fmaxf(acc[j][2] + b2, 0.f);
        r.w = fmaxf(acc[j][3] + b3, 0.f);
        *(float4*)&g_R[((size_t)b * NPTS + n) * 64 + to * 4] = r;
    }
}

// ---------------------------------------------------------------------------
// Stage 2: out[b][o][n] = R[b][n][o] + sum_k R[b][idx[b][n][k]][o]
// Block: 512 threads, tile = 32 points. 64 threads (one per o) per point,
// 8 points per pass, 4 passes. Shared transpose -> coalesced float4 stores.
// ---------------------------------------------------------------------------
__global__ __launch_bounds__(512) void spe_stage2(
    const int* __restrict__ nidx,
    float* __restrict__ out)
{
    __shared__ float s[64][36];   // [o][n_local], pad 36 (144B: 16B-aligned rows, no bank conflicts)

    const int b   = blockIdx.y;
    const int n0  = blockIdx.x * 32;
    const int tid = threadIdx.x;
    const int o   = tid & 63;
    const int pg  = tid >> 6;     // 0..7

    const float* __restrict__ Rb = g_R + (size_t)b * NPTS * 64;

    #pragma unroll
    for (int p = 0; p < 4; p++) {
        const int nl = p * 8 + pg;
        const int n  = n0 + nl;

        float acc = Rb[(size_t)n * 64 + o];

        const int4* ip = (const int4*)(nidx + ((size_t)b * NPTS + n) * KNB);
        int4 i0 = ip[0], i1 = ip[1], i2 = ip[2], i3 = ip[3];

        // Issue all 16 gathers before reducing (MLP=16, L2-resident)
        float v0  = Rb[(size_t)i0.x * 64 + o];
        float v1  = Rb[(size_t)i0.y * 64 + o];
        float v2  = Rb[(size_t)i0.z * 64 + o];
        float v3  = Rb[(size_t)i0.w * 64 + o];
        float v4  = Rb[(size_t)i1.x * 64 + o];
        float v5  = Rb[(size_t)i1.y * 64 + o];
        float v6  = Rb[(size_t)i1.z * 64 + o];
        float v7  = Rb[(size_t)i1.w * 64 + o];
        float v8  = Rb[(size_t)i2.x * 64 + o];
        float v9  = Rb[(size_t)i2.y * 64 + o];
        float v10 = Rb[(size_t)i2.z * 64 + o];
        float v11 = Rb[(size_t)i2.w * 64 + o];
        float v12 = Rb[(size_t)i3.x * 64 + o];
        float v13 = Rb[(size_t)i3.y * 64 + o];
        float v14 = Rb[(size_t)i3.z * 64 + o];
        float v15 = Rb[(size_t)i3.w * 64 + o];

        acc += ((v0 + v1) + (v2 + v3)) + ((v4 + v5) + (v6 + v7))
             + ((v8 + v9) + (v10 + v11)) + ((v12 + v13) + (v14 + v15));

        s[o][nl] = acc;
    }
    __syncthreads();

    // Coalesced write-out: out[b][o][n0..n0+31], 512 threads x float4
    const int oo = tid >> 3;        // 0..63
    const int q  = tid & 7;         // 0..7
    float4 r = *(float4*)&s[oo][q * 4];
    *(float4*)&out[((size_t)b * 64 + oo) * NPTS + n0 + q * 4] = r;
}

extern "C" void kernel_launch(void* const* d_in, const int* in_sizes, int n_in,
                              void* d_out, int out_size) {
    const float* feature = (const float*)d_in[0];
    const int*   nidx    = (const int*)d_in[1];
    const float* W       = (const float*)d_in[2];
    const float* gamma   = (const float*)d_in[3];
    const float* beta    = (const float*)d_in[4];
    const float* rmean   = (const float*)d_in[5];
    const float* rvar    = (const float*)d_in[6];
    float* out = (float*)d_out;

    const int B = in_sizes[0] / (NCH * NPTS);   // = 2

    dim3 g1(NPTS / 64, B);
    spe_stage1<<<g1, 256>>>(feature, W, gamma, beta, rmean, rvar);

    dim3 g2(NPTS / 32, B);
    spe_stage2<<<g2, 512>>>(nidx, out);
}

// round 2
// speedup vs baseline: 1.2272x; 1.2272x over previous
#include <cuda_runtime.h>
#include <cuda_fp16.h>

#define NPTS 32768
#define NCH  64     // C == O == 64
#define KNB  16

// Post-BN/ReLU transformed features in fp16, layout [b][n][o] (o contiguous).
// 2 * 32768 * 64 halves = 8.4 MB  (L2-resident during stage 2)
__device__ __half g_Rh[2 * NPTS * NCH];

#define PACK2(d, x, y) \
    asm("mov.b64 %0, {%1, %2};" : "=l"(d) : "r"(__float_as_uint(x)), "r"(__float_as_uint(y)))
#define UNPACK2(x, y, d) do { unsigned _lo, _hi; \
    asm("mov.b64 {%0, %1}, %2;" : "=r"(_lo), "=r"(_hi) : "l"(d)); \
    x = __uint_as_float(_lo); y = __uint_as_float(_hi); } while (0)
#define FMA2(d, a, b, c) \
    asm("fma.rn.f32x2 %0, %1, %2, %3;" : "=l"(d) : "l"(a), "l"(b), "l"(c))

// ---------------------------------------------------------------------------
// Stage 1: R[b][n][o] = relu( sum_c W[o][c]*inv[o] * feat[b][c][n] + bias[o] )
// Packed f32x2 FMA over o-pairs. Block 256, tile 64o x 64n, micro 4o x 4n.
// ---------------------------------------------------------------------------
__global__ __launch_bounds__(256) void spe_stage1(
    const float* __restrict__ feat,
    const float* __restrict__ W,
    const float* __restrict__ gamma,
    const float* __restrict__ beta,
    const float* __restrict__ rmean,
    const float* __restrict__ rvar)
{
    __shared__ float sWt[64][64];   // [c][o], pre-scaled by inv[o]
    __shared__ float sBias[64];
    __shared__ float sF[64][64];    // [c][n_local]

    const int b   = blockIdx.y;
    const int n0  = blockIdx.x * 64;
    const int tid = threadIdx.x;

    #pragma unroll
    for (int e = tid; e < 64 * 64; e += 256) {
        int o = e & 63, c = e >> 6;
        float inv = gamma[o] * rsqrtf(rvar[o] + 1e-5f);
        sWt[c][o] = W[o * 64 + c] * inv;
    }
    if (tid < 64) {
        float inv = gamma[tid] * rsqrtf(rvar[tid] + 1e-5f);
        sBias[tid] = beta[tid] - rmean[tid] * inv;
    }

    #pragma unroll
    for (int it = 0; it < 4; it++) {
        int idx = it * 256 + tid;
        int c = idx >> 4, v = idx & 15;
        *(float4*)&sF[c][v * 4] =
            *(const float4*)&feat[((size_t)b * 64 + c) * NPTS + n0 + v * 4];
    }
    __syncthreads();

    const int to = tid & 15;   // o-group: o = to*4 .. to*4+3
    const int tn = tid >> 4;   // n-group: n = tn*4 .. tn*4+3

    // acc[j][i]: packed pair (o = to*4+2i, +1) for n = tn*4+j
    unsigned long long acc[4][2];
    #pragma unroll
    for (int j = 0; j < 4; j++) { acc[j][0] = 0ull; acc[j][1] = 0ull; }

    #pragma unroll 16
    for (int c = 0; c < 64; c++) {
        float4 w = *(float4*)&sWt[c][to * 4];
        float4 f = *(float4*)&sF[c][tn * 4];
        unsigned long long wp0, wp1, fd;
        PACK2(wp0, w.x, w.y);
        PACK2(wp1, w.z, w.w);
        PACK2(fd, f.x, f.x);
        FMA2(acc[0][0], wp0, fd, acc[0][0]); FMA2(acc[0][1], wp1, fd, acc[0][1]);
        PACK2(fd, f.y, f.y);
        FMA2(acc[1][0], wp0, fd, acc[1][0]); FMA2(acc[1][1], wp1, fd, acc[1][1]);
        PACK2(fd, f.z, f.z);
        FMA2(acc[2][0], wp0, fd, acc[2][0]); FMA2(acc[2][1], wp1, fd, acc[2][1]);
        PACK2(fd, f.w, f.w);
        FMA2(acc[3][0], wp0, fd, acc[3][0]); FMA2(acc[3][1], wp1, fd, acc[3][1]);
    }

    float b0 = sBias[to * 4 + 0];
    float b1 = sBias[to * 4 + 1];
    float b2 = sBias[to * 4 + 2];
    float b3 = sBias[to * 4 + 3];

    __half* Rrow = g_Rh + (size_t)b * NPTS * 64;
    #pragma unroll
    for (int j = 0; j < 4; j++) {
        int n = n0 + tn * 4 + j;
        float v0, v1, v2, v3;
        UNPACK2(v0, v1, acc[j][0]);
        UNPACK2(v2, v3, acc[j][1]);
        __half2 h01 = __floats2half2_rn(fmaxf(v0 + b0, 0.f), fmaxf(v1 + b1, 0.f));
        __half2 h23 = __floats2half2_rn(fmaxf(v2 + b2, 0.f), fmaxf(v3 + b3, 0.f));
        uint2 u;
        u.x = *(unsigned*)&h01;
        u.y = *(unsigned*)&h23;
        *(uint2*)&Rrow[(size_t)n * 64 + to * 4] = u;
    }
}

// ---------------------------------------------------------------------------
// Stage 2: out[b][o][n] = R[b][n][o] + sum_k R[b][idx[b][n][k]][o]
// 8 threads per point, each gathers 16B (8 halves) per neighbor, fp32 accum.
// Block 256 threads = 32 points. Shared transpose -> coalesced stores.
// ---------------------------------------------------------------------------
__device__ __forceinline__ void acc8(float* a, uint4 v) {
    float2 t;
    t = __half22float2(*(__half2*)&v.x); a[0] += t.x; a[1] += t.y;
    t = __half22float2(*(__half2*)&v.y); a[2] += t.x; a[3] += t.y;
    t = __half22float2(*(__half2*)&v.z); a[4] += t.x; a[5] += t.y;
    t = __half22float2(*(__half2*)&v.w); a[6] += t.x; a[7] += t.y;
}

__global__ __launch_bounds__(256) void spe_stage2(
    const int* __restrict__ nidx,
    float* __restrict__ out)
{
    __shared__ float s[32][68];   // [p][o], stride 68 floats (16B-aligned rows)

    const int b   = blockIdx.y;
    const int n0  = blockIdx.x * 32;
    const int tid = threadIdx.x;
    const int p   = tid >> 3;     // point in tile: 0..31
    const int g   = tid & 7;      // 16B segment within 128B row
    const int n   = n0 + p;

    const __half* __restrict__ Rb = g_Rh + (size_t)b * NPTS * 64;

    const int4* ip = (const int4*)(nidx + ((size_t)b * NPTS + n) * KNB);
    int4 i0 = ip[0], i1 = ip[1], i2 = ip[2], i3 = ip[3];

    float a[8];
    #pragma unroll
    for (int j = 0; j < 8; j++) a[j] = 0.f;

    // self row + 4 waves of 4 gathers (MLP >= 4x16B per thread)
    uint4 vs = ((const uint4*)(Rb + ((size_t)n << 6)))[g];
    uint4 va = ((const uint4*)(Rb + ((size_t)i0.x << 6)))[g];
    uint4 vb = ((const uint4*)(Rb + ((size_t)i0.y << 6)))[g];
    uint4 vc = ((const uint4*)(Rb + ((size_t)i0.z << 6)))[g];
    uint4 vd = ((const uint4*)(Rb + ((size_t)i0.w << 6)))[g];
    acc8(a, vs);
    uint4 ve = ((const uint4*)(Rb + ((size_t)i1.x << 6)))[g];
    uint4 vf = ((const uint4*)(Rb + ((size_t)i1.y << 6)))[g];
    uint4 vg = ((const uint4*)(Rb + ((size_t)i1.z << 6)))[g];
    uint4 vh = ((const uint4*)(Rb + ((size_t)i1.w << 6)))[g];
    acc8(a, va); acc8(a, vb); acc8(a, vc); acc8(a, vd);
    va = ((const uint4*)(Rb + ((size_t)i2.x << 6)))[g];
    vb = ((const uint4*)(Rb + ((size_t)i2.y << 6)))[g];
    vc = ((const uint4*)(Rb + ((size_t)i2.z << 6)))[g];
    vd = ((const uint4*)(Rb + ((size_t)i2.w << 6)))[g];
    acc8(a, ve); acc8(a, vf); acc8(a, vg); acc8(a, vh);
    ve = ((const uint4*)(Rb + ((size_t)i3.x << 6)))[g];
    vf = ((const uint4*)(Rb + ((size_t)i3.y << 6)))[g];
    vg = ((const uint4*)(Rb + ((size_t)i3.z << 6)))[g];
    vh = ((const uint4*)(Rb + ((size_t)i3.w << 6)))[g];
    acc8(a, va); acc8(a, vb); acc8(a, vc); acc8(a, vd);
    acc8(a, ve); acc8(a, vf); acc8(a, vg); acc8(a, vh);

    // write accumulators: channels o = g*8 .. g*8+7 for point p
    *(float4*)&s[p][g * 8]     = make_float4(a[0], a[1], a[2], a[3]);
    *(float4*)&s[p][g * 8 + 4] = make_float4(a[4], a[5], a[6], a[7]);
    __syncthreads();

    // coalesced write-out: out[b][o][n0..n0+31]
    const int o = tid & 63;
    const int q = tid >> 6;    // 0..3
    #pragma unroll
    for (int h = 0; h < 2; h++) {
        int qq = q + h * 4;    // 0..7: n chunk of 4 points
        float4 r;
        r.x = s[qq * 4 + 0][o];
        r.y = s[qq * 4 + 1][o];
        r.z = s[qq * 4 + 2][o];
        r.w = s[qq * 4 + 3][o];
        *(float4*)&out[((size_t)b * 64 + o) * NPTS + n0 + qq * 4] = r;
    }
}

extern "C" void kernel_launch(void* const* d_in, const int* in_sizes, int n_in,
                              void* d_out, int out_size) {
    const float* feature = (const float*)d_in[0];
    const int*   nidx    = (const int*)d_in[1];
    const float* W       = (const float*)d_in[2];
    const float* gamma   = (const float*)d_in[3];
    const float* beta    = (const float*)d_in[4];
    const float* rmean   = (const float*)d_in[5];
    const float* rvar    = (const float*)d_in[6];
    float* out = (float*)d_out;

    const int B = in_sizes[0] / (NCH * NPTS);   // = 2

    dim3 g1(NPTS / 64, B);
    spe_stage1<<<g1, 256>>>(feature, W, gamma, beta, rmean, rvar);

    dim3 g2(NPTS / 32, B);
    spe_stage2<<<g2, 256>>>(nidx, out);
}

// round 6
// speedup vs baseline: 1.9923x; 1.6235x over previous
#include <cuda_runtime.h>
#include <cuda_fp16.h>
#include <cstdint>

#define NPTS 32768
#define KNB  16

// Post-BN/ReLU features fp16, layout [b][n][o] (o contiguous). 8.4 MB, L2-resident.
__device__ __half g_Rh[2 * NPTS * 64];

#define SWZ(x) ((x) ^ (((x) >> 3) & 0x70))

__device__ __forceinline__ uint32_t smem_u32(const void* p) {
    uint32_t a;
    asm("{ .reg .u64 t; cvta.to.shared.u64 t, %1; cvt.u32.u64 %0, t; }" : "=r"(a) : "l"(p));
    return a;
}

#define LDSM4(r, addr) \
    asm volatile("ldmatrix.sync.aligned.m8n8.x4.shared.b16 {%0,%1,%2,%3}, [%4];" \
        : "=r"((r)[0]), "=r"((r)[1]), "=r"((r)[2]), "=r"((r)[3]) : "r"(addr))

#define MMA16816(d, a, b0, b1) \
    asm volatile("mma.sync.aligned.m16n8k16.row.col.f32.f16.f16.f32 " \
        "{%0,%1,%2,%3}, {%4,%5,%6,%7}, {%8,%9}, {%0,%1,%2,%3};" \
        : "+f"((d)[0]), "+f"((d)[1]), "+f"((d)[2]), "+f"((d)[3]) \
        : "r"((a)[0]), "r"((a)[1]), "r"((a)[2]), "r"((a)[3]), "r"(b0), "r"(b1))

// ---------------------------------------------------------------------------
// Stage 1 (HMMA): R[b][n][o] = relu( F[128n x 64c] @ Ws[64o x 64c]^T + bias )
// ---------------------------------------------------------------------------
__global__ __launch_bounds__(128) void spe_stage1(
    const float* __restrict__ feat,
    const float* __restrict__ W,
    const float* __restrict__ gamma,
    const float* __restrict__ beta,
    const float* __restrict__ rmean,
    const float* __restrict__ rvar)
{
    __shared__ __align__(128) char sA[128 * 128];  // F tile [n][c] fp16, SW128; reused for output
    __shared__ __align__(128) char sW[64 * 128];   // Ws [o][c] fp16, SW128
    __shared__ float sBias[64];

    const int tid = threadIdx.x, wid = tid >> 5, lane = tid & 31;
    const int b  = blockIdx.y;
    const int n0 = blockIdx.x * 128;

    if (tid < 64) {
        float inv = gamma[tid] * rsqrtf(rvar[tid] + 1e-5f);
        sBias[tid] = beta[tid] - rmean[tid] * inv;
    }

    // Ws[o][c] = W[o][c] * inv[o], fp16, rows of 128B (64 halves)
    #pragma unroll
    for (int e = tid; e < 2048; e += 128) {
        int o = e >> 5, c2 = e & 31;
        float inv = gamma[o] * rsqrtf(rvar[o] + 1e-5f);
        float2 w2 = *(const float2*)&W[o * 64 + c2 * 2];
        __half2 h = __floats2half2_rn(w2.x * inv, w2.y * inv);
        *(uint32_t*)(sW + SWZ(o * 128 + c2 * 4)) = *(uint32_t*)&h;
    }

    // F[n][c] fp16: transpose-convert from feat[b][c][n0..n0+127]
    #pragma unroll
    for (int e = tid; e < 1024; e += 128) {
        int c2 = e >> 5, nq = e & 31;   // c-pair, n-quad
        const float* p0 = &feat[((size_t)b * 64 + 2 * c2) * NPTS + n0 + nq * 4];
        float4 f0 = *(const float4*)p0;
        float4 f1 = *(const float4*)(p0 + NPTS);
        __half2 h0 = __floats2half2_rn(f0.x, f1.x);
        __half2 h1 = __floats2half2_rn(f0.y, f1.y);
        __half2 h2 = __floats2half2_rn(f0.z, f1.z);
        __half2 h3 = __floats2half2_rn(f0.w, f1.w);
        int nl = nq * 4;
        *(uint32_t*)(sA + SWZ((nl + 0) * 128 + c2 * 4)) = *(uint32_t*)&h0;
        *(uint32_t*)(sA + SWZ((nl + 1) * 128 + c2 * 4)) = *(uint32_t*)&h1;
        *(uint32_t*)(sA + SWZ((nl + 2) * 128 + c2 * 4)) = *(uint32_t*)&h2;
        *(uint32_t*)(sA + SWZ((nl + 3) * 128 + c2 * 4)) = *(uint32_t*)&h3;
    }
    __syncthreads();

    const uint32_t smA = smem_u32(sA), smW = smem_u32(sW);

    float acc[2][8][4];
    #pragma unroll
    for (int t = 0; t < 2; t++)
        #pragma unroll
        for (int j = 0; j < 8; j++)
            #pragma unroll
            for (int q = 0; q < 4; q++) acc[t][j][q] = 0.f;

    // ldmatrix per-lane base byte offsets (before k-step advance)
    // A x4: mat = lane>>3: (rows0-7,k0-7),(rows8-15,k0-7),(rows0-7,k8-15),(rows8-15,k8-15)
    int aBase[2];
    {
        int row_in = (lane & 7) + ((lane >> 3) & 1) * 8;
        int kchunk = ((lane >> 4) & 1) * 16;
        #pragma unroll
        for (int t = 0; t < 2; t++)
            aBase[t] = (wid * 32 + t * 16 + row_in) * 128 + kchunk;
    }
    // B x4 (pair jj covers n-tiles 2jj, 2jj+1): mat = lane>>3:
    //   (ntile 2jj, k0-7),(ntile 2jj, k8-15),(ntile 2jj+1, k0-7),(ntile 2jj+1, k8-15)
    int bBase[4];
    {
        int row_in = lane & 7;
        int nsel   = (lane >> 4) & 1;      // mat>>1
        int kchunk = ((lane >> 3) & 1) * 16; // mat&1
        #pragma unroll
        for (int jj = 0; jj < 4; jj++)
            bBase[jj] = ((2 * jj + nsel) * 8 + row_in) * 128 + kchunk;
    }

    #pragma unroll
    for (int k = 0; k < 4; k++) {
        uint32_t af[2][4], bf[4][4];
        #pragma unroll
        for (int t = 0; t < 2; t++)
            LDSM4(af[t], smA + SWZ(aBase[t] + k * 32));
        #pragma unroll
        for (int jj = 0; jj < 4; jj++)
            LDSM4(bf[jj], smW + SWZ(bBase[jj] + k * 32));
        #pragma unroll
        for (int t = 0; t < 2; t++)
            #pragma unroll
            for (int j = 0; j < 8; j++)
                MMA16816(acc[t][j], af[t], bf[j >> 1][(j & 1) * 2], bf[j >> 1][(j & 1) * 2 + 1]);
    }

    __syncthreads();   // done reading sA/sW; reuse sA for output staging

    // Epilogue: bias + relu -> fp16, staged into sA (swizzled), rows = n
    const int r0 = wid * 32 + (lane >> 2);
    const int cq = lane & 3;                 // col pair (lane%4)*2 within n8 tile
    #pragma unroll
    for (int t = 0; t < 2; t++) {
        #pragma unroll
        for (int j = 0; j < 8; j++) {
            float2 bb = *(float2*)&sBias[j * 8 + cq * 2];
            __half2 h01 = __floats2half2_rn(fmaxf(acc[t][j][0] + bb.x, 0.f),
                                            fmaxf(acc[t][j][1] + bb.y, 0.f));
            __half2 h23 = __floats2half2_rn(fmaxf(acc[t][j][2] + bb.x, 0.f),
                                            fmaxf(acc[t][j][3] + bb.y, 0.f));
            int colb = j * 16 + cq * 4;
            *(uint32_t*)(sA + SWZ((r0 + t * 16) * 128 + colb))     = *(uint32_t*)&h01;
            *(uint32_t*)(sA + SWZ((r0 + t * 16 + 8) * 128 + colb)) = *(uint32_t*)&h23;
        }
    }
    __syncthreads();

    // Coalesced copy-out: 128 rows x 128B
    __half* Rb = g_Rh + (((size_t)b * NPTS + n0) << 6);
    #pragma unroll
    for (int i = tid; i < 1024; i += 128) {
        int row = i >> 3, seg = i & 7;
        uint4 v = *(uint4*)(sA + SWZ(row * 128 + seg * 16));
        *(uint4*)(Rb + ((size_t)row << 6) + seg * 8) = v;
    }
}

// ---------------------------------------------------------------------------
// Stage 2: out[b][o][n] = R[b][n][o] + sum_k R[b][idx[n][k]][o]
// 16 threads/point, 8B (4-channel) gathers, fp32 accum. Block 256 = 16 points.
// ---------------------------------------------------------------------------
__device__ __forceinline__ void acc4(float& a0, float& a1, float& a2, float& a3, uint2 v) {
    float2 t0 = __half22float2(*(__half2*)&v.x);
    float2 t1 = __half22float2(*(__half2*)&v.y);
    a0 += t0.x; a1 += t0.y; a2 += t1.x; a3 += t1.y;
}

__global__ __launch_bounds__(256) void spe_stage2(
    const int* __restrict__ nidx,
    float* __restrict__ out)
{
    __shared__ float s[16][68];

    const int b   = blockIdx.y;
    const int n0  = blockIdx.x * 16;
    const int tid = threadIdx.x;
    const int p   = tid >> 4;     // point 0..15
    const int g   = tid & 15;     // 8B segment
    const int n   = n0 + p;

    const __half* __restrict__ Rb = g_Rh + ((size_t)b << 21);

    const int4* ip = (const int4*)(nidx + ((size_t)(b * NPTS + n)) * KNB);
    int4 i0 = ip[0], i1 = ip[1], i2 = ip[2], i3 = ip[3];

    float a0 = 0.f, a1 = 0.f, a2 = 0.f, a3 = 0.f;

    #define LD8(idx) (((const uint2*)(Rb + ((size_t)(idx) << 6)))[g])
    uint2 v0 = LD8(n);
    uint2 v1 = LD8(i0.x); uint2 v2 = LD8(i0.y); uint2 v3 = LD8(i0.z); uint2 v4 = LD8(i0.w);
    uint2 v5 = LD8(i1.x); uint2 v6 = LD8(i1.y); uint2 v7 = LD8(i1.z); uint2 v8 = LD8(i1.w);
    acc4(a0, a1, a2, a3, v0);
    acc4(a0, a1, a2, a3, v1); acc4(a0, a1, a2, a3, v2);
    acc4(a0, a1, a2, a3, v3); acc4(a0, a1, a2, a3, v4);
    uint2 w1 = LD8(i2.x); uint2 w2 = LD8(i2.y); uint2 w3 = LD8(i2.z); uint2 w4 = LD8(i2.w);
    uint2 w5 = LD8(i3.x); uint2 w6 = LD8(i3.y); uint2 w7 = LD8(i3.z); uint2 w8 = LD8(i3.w);
    acc4(a0, a1, a2, a3, v5); acc4(a0, a1, a2, a3, v6);
    acc4(a0, a1, a2, a3, v7); acc4(a0, a1, a2, a3, v8);
    acc4(a0, a1, a2, a3, w1); acc4(a0, a1, a2, a3, w2);
    acc4(a0, a1, a2, a3, w3); acc4(a0, a1, a2, a3, w4);
    acc4(a0, a1, a2, a3, w5); acc4(a0, a1, a2, a3, w6);
    acc4(a0, a1, a2, a3, w7); acc4(a0, a1, a2, a3, w8);
    #undef LD8

    *(float4*)&s[p][g * 4] = make_float4(a0, a1, a2, a3);
    __syncthreads();

    // coalesced write-out: out[b][o][n0..n0+15]
    const int o   = tid & 63;
    const int grp = tid >> 6;   // 0..3 -> 4 points each
    float4 r;
    r.x = s[grp * 4 + 0][o];
    r.y = s[grp * 4 + 1][o];
    r.z = s[grp * 4 + 2][o];
    r.w = s[grp * 4 + 3][o];
    *(float4*)&out[((size_t)b * 64 + o) * NPTS + n0 + grp * 4] = r;
}

extern "C" void kernel_launch(void* const* d_in, const int* in_sizes, int n_in,
                              void* d_out, int out_size) {
    const float* feature = (const float*)d_in[0];
    const int*   nidx    = (const int*)d_in[1];
    const float* W       = (const float*)d_in[2];
    const float* gamma   = (const float*)d_in[3];
    const float* beta    = (const float*)d_in[4];
    const float* rmean   = (const float*)d_in[5];
    const float* rvar    = (const float*)d_in[6];
    float* out = (float*)d_out;

    const int B = in_sizes[0] / (64 * NPTS);   // = 2

    dim3 g1(NPTS / 128, B);
    spe_stage1<<<g1, 128>>>(feature, W, gamma, beta, rmean, rvar);

    dim3 g2(NPTS / 16, B);
    spe_stage2<<<g2, 256>>>(nidx, out);
}

// round 7
// speedup vs baseline: 2.1403x; 1.0743x over previous
#include <cuda_runtime.h>
#include <cuda_fp16.h>
#include <cstdint>

#define NPTS 32768
#define KNB  16

// Post-BN/ReLU features fp16, layout [b][n][o] (o contiguous). 8.4 MB, L2-resident.
__device__ __half g_Rh[2 * NPTS * 64];

#define SWZ(x) ((x) ^ (((x) >> 3) & 0x70))

__device__ __forceinline__ uint32_t smem_u32(const void* p) {
    uint32_t a;
    asm("{ .reg .u64 t; cvta.to.shared.u64 t, %1; cvt.u32.u64 %0, t; }" : "=r"(a) : "l"(p));
    return a;
}

#define LDSM4(r, addr) \
    asm volatile("ldmatrix.sync.aligned.m8n8.x4.shared.b16 {%0,%1,%2,%3}, [%4];" \
        : "=r"((r)[0]), "=r"((r)[1]), "=r"((r)[2]), "=r"((r)[3]) : "r"(addr))

#define MMA16816(d, a, b0, b1) \
    asm volatile("mma.sync.aligned.m16n8k16.row.col.f32.f16.f16.f32 " \
        "{%0,%1,%2,%3}, {%4,%5,%6,%7}, {%8,%9}, {%0,%1,%2,%3};" \
        : "+f"((d)[0]), "+f"((d)[1]), "+f"((d)[2]), "+f"((d)[3]) \
        : "r"((a)[0]), "r"((a)[1]), "r"((a)[2]), "r"((a)[3]), "r"(b0), "r"(b1))

// ---------------------------------------------------------------------------
// Stage 1 (HMMA): R[b][n][o] = relu( F[64n x 64c] @ Ws[64o x 64c]^T + bias )
// 64-point tile per CTA -> 1024 CTAs for latency hiding on DRAM loads.
// ---------------------------------------------------------------------------
__global__ __launch_bounds__(128) void spe_stage1(
    const float* __restrict__ feat,
    const float* __restrict__ W,
    const float* __restrict__ gamma,
    const float* __restrict__ beta,
    const float* __restrict__ rmean,
    const float* __restrict__ rvar)
{
    __shared__ __align__(128) char sA[64 * 128];   // F tile [n][c] fp16, SW128; reused for output
    __shared__ __align__(128) char sW[64 * 128];   // Ws [o][c] fp16, SW128
    __shared__ float sBias[64];

    const int tid = threadIdx.x, wid = tid >> 5, lane = tid & 31;
    const int b  = blockIdx.y;
    const int n0 = blockIdx.x * 64;

    if (tid < 64) {
        float inv = gamma[tid] * rsqrtf(rvar[tid] + 1e-5f);
        sBias[tid] = beta[tid] - rmean[tid] * inv;
    }

    // Ws[o][c] = W[o][c] * inv[o], fp16, rows of 128B (64 halves)
    #pragma unroll
    for (int e = tid; e < 2048; e += 128) {
        int o = e >> 5, c2 = e & 31;
        float inv = gamma[o] * rsqrtf(rvar[o] + 1e-5f);
        float2 w2 = *(const float2*)&W[o * 64 + c2 * 2];
        __half2 h = __floats2half2_rn(w2.x * inv, w2.y * inv);
        *(uint32_t*)(sW + SWZ(o * 128 + c2 * 4)) = *(uint32_t*)&h;
    }

    // F[n][c] fp16: transpose-convert from feat[b][c][n0..n0+63]
    #pragma unroll
    for (int e = tid; e < 512; e += 128) {
        int c2 = e >> 4, nq = e & 15;   // c-pair, n-quad
        const float* p0 = &feat[((size_t)b * 64 + 2 * c2) * NPTS + n0 + nq * 4];
        float4 f0 = *(const float4*)p0;
        float4 f1 = *(const float4*)(p0 + NPTS);
        __half2 h0 = __floats2half2_rn(f0.x, f1.x);
        __half2 h1 = __floats2half2_rn(f0.y, f1.y);
        __half2 h2 = __floats2half2_rn(f0.z, f1.z);
        __half2 h3 = __floats2half2_rn(f0.w, f1.w);
        int nl = nq * 4;
        *(uint32_t*)(sA + SWZ((nl + 0) * 128 + c2 * 4)) = *(uint32_t*)&h0;
        *(uint32_t*)(sA + SWZ((nl + 1) * 128 + c2 * 4)) = *(uint32_t*)&h1;
        *(uint32_t*)(sA + SWZ((nl + 2) * 128 + c2 * 4)) = *(uint32_t*)&h2;
        *(uint32_t*)(sA + SWZ((nl + 3) * 128 + c2 * 4)) = *(uint32_t*)&h3;
    }
    __syncthreads();

    const uint32_t smA = smem_u32(sA), smW = smem_u32(sW);

    float acc[8][4];
    #pragma unroll
    for (int j = 0; j < 8; j++)
        #pragma unroll
        for (int q = 0; q < 4; q++) acc[j][q] = 0.f;

    // ldmatrix per-lane base byte offsets
    int aBase;
    {
        int row_in = (lane & 7) + ((lane >> 3) & 1) * 8;
        int kchunk = ((lane >> 4) & 1) * 16;
        aBase = (wid * 16 + row_in) * 128 + kchunk;
    }
    int bBase[4];
    {
        int row_in = lane & 7;
        int nsel   = (lane >> 4) & 1;
        int kchunk = ((lane >> 3) & 1) * 16;
        #pragma unroll
        for (int jj = 0; jj < 4; jj++)
            bBase[jj] = ((2 * jj + nsel) * 8 + row_in) * 128 + kchunk;
    }

    #pragma unroll
    for (int k = 0; k < 4; k++) {
        uint32_t af[4], bf[4][4];
        LDSM4(af, smA + SWZ(aBase + k * 32));
        #pragma unroll
        for (int jj = 0; jj < 4; jj++)
            LDSM4(bf[jj], smW + SWZ(bBase[jj] + k * 32));
        #pragma unroll
        for (int j = 0; j < 8; j++)
            MMA16816(acc[j], af, bf[j >> 1][(j & 1) * 2], bf[j >> 1][(j & 1) * 2 + 1]);
    }

    __syncthreads();   // done reading sA/sW; reuse sA for output staging

    // Epilogue: bias + relu -> fp16, staged into sA (swizzled), rows = n
    const int r0 = wid * 16 + (lane >> 2);
    const int cq = lane & 3;
    #pragma unroll
    for (int j = 0; j < 8; j++) {
        float2 bb = *(float2*)&sBias[j * 8 + cq * 2];
        __half2 h01 = __floats2half2_rn(fmaxf(acc[j][0] + bb.x, 0.f),
                                        fmaxf(acc[j][1] + bb.y, 0.f));
        __half2 h23 = __floats2half2_rn(fmaxf(acc[j][2] + bb.x, 0.f),
                                        fmaxf(acc[j][3] + bb.y, 0.f));
        int colb = j * 16 + cq * 4;
        *(uint32_t*)(sA + SWZ(r0 * 128 + colb))       = *(uint32_t*)&h01;
        *(uint32_t*)(sA + SWZ((r0 + 8) * 128 + colb)) = *(uint32_t*)&h23;
    }
    __syncthreads();

    // Coalesced copy-out: 64 rows x 128B
    __half* Rb = g_Rh + (((size_t)b * NPTS + n0) << 6);
    #pragma unroll
    for (int i = tid; i < 512; i += 128) {
        int row = i >> 3, seg = i & 7;
        uint4 v = *(uint4*)(sA + SWZ(row * 128 + seg * 16));
        *(uint4*)(Rb + ((size_t)row << 6) + seg * 8) = v;
    }
}

// ---------------------------------------------------------------------------
// Stage 2: out[b][o][n] = R[b][n][o] + sum_k R[b][idx[n][k]][o]
// 16 threads/point, 8B gathers via __ldcg (L2-only, no L1 allocate).
// ---------------------------------------------------------------------------
__device__ __forceinline__ void acc4(float& a0, float& a1, float& a2, float& a3, uint2 v) {
    float2 t0 = __half22float2(*(__half2*)&v.x);
    float2 t1 = __half22float2(*(__half2*)&v.y);
    a0 += t0.x; a1 += t0.y; a2 += t1.x; a3 += t1.y;
}

__global__ __launch_bounds__(256) void spe_stage2(
    const int* __restrict__ nidx,
    float* __restrict__ out)
{
    __shared__ float s[16][68];

    const int b   = blockIdx.y;
    const int n0  = blockIdx.x * 16;
    const int tid = threadIdx.x;
    const int p   = tid >> 4;     // point 0..15
    const int g   = tid & 15;     // 8B segment
    const int n   = n0 + p;

    const __half* __restrict__ Rb = g_Rh + ((size_t)b << 21);

    const int4* ip = (const int4*)(nidx + ((size_t)(b * NPTS + n)) * KNB);
    int4 i0 = ip[0], i1 = ip[1], i2 = ip[2], i3 = ip[3];

    float a0 = 0.f, a1 = 0.f, a2 = 0.f, a3 = 0.f;

    #define LD8(idx) __ldcg((const uint2*)(Rb + ((size_t)(idx) << 6)) + g)
    uint2 v0 = LD8(n);
    uint2 v1 = LD8(i0.x); uint2 v2 = LD8(i0.y); uint2 v3 = LD8(i0.z); uint2 v4 = LD8(i0.w);
    uint2 v5 = LD8(i1.x); uint2 v6 = LD8(i1.y); uint2 v7 = LD8(i1.z); uint2 v8 = LD8(i1.w);
    acc4(a0, a1, a2, a3, v0);
    acc4(a0, a1, a2, a3, v1); acc4(a0, a1, a2, a3, v2);
    acc4(a0, a1, a2, a3, v3); acc4(a0, a1, a2, a3, v4);
    uint2 w1 = LD8(i2.x); uint2 w2 = LD8(i2.y); uint2 w3 = LD8(i2.z); uint2 w4 = LD8(i2.w);
    uint2 w5 = LD8(i3.x); uint2 w6 = LD8(i3.y); uint2 w7 = LD8(i3.z); uint2 w8 = LD8(i3.w);
    acc4(a0, a1, a2, a3, v5); acc4(a0, a1, a2, a3, v6);
    acc4(a0, a1, a2, a3, v7); acc4(a0, a1, a2, a3, v8);
    acc4(a0, a1, a2, a3, w1); acc4(a0, a1, a2, a3, w2);
    acc4(a0, a1, a2, a3, w3); acc4(a0, a1, a2, a3, w4);
    acc4(a0, a1, a2, a3, w5); acc4(a0, a1, a2, a3, w6);
    acc4(a0, a1, a2, a3, w7); acc4(a0, a1, a2, a3, w8);
    #undef LD8

    *(float4*)&s[p][g * 4] = make_float4(a0, a1, a2, a3);
    __syncthreads();

    // coalesced write-out: out[b][o][n0..n0+15]
    const int o   = tid & 63;
    const int grp = tid >> 6;   // 0..3 -> 4 points each
    float4 r;
    r.x = s[grp * 4 + 0][o];
    r.y = s[grp * 4 + 1][o];
    r.z = s[grp * 4 + 2][o];
    r.w = s[grp * 4 + 3][o];
    *(float4*)&out[((size_t)b * 64 + o) * NPTS + n0 + grp * 4] = r;
}

extern "C" void kernel_launch(void* const* d_in, const int* in_sizes, int n_in,
                              void* d_out, int out_size) {
    const float* feature = (const float*)d_in[0];
    const int*   nidx    = (const int*)d_in[1];
    const float* W       = (const float*)d_in[2];
    const float* gamma   = (const float*)d_in[3];
    const float* beta    = (const float*)d_in[4];
    const float* rmean   = (const float*)d_in[5];
    const float* rvar    = (const float*)d_in[6];
    float* out = (float*)d_out;

    const int B = in_sizes[0] / (64 * NPTS);   // = 2

    dim3 g1(NPTS / 64, B);
    spe_stage1<<<g1, 128>>>(feature, W, gamma, beta, rmean, rvar);

    dim3 g2(NPTS / 16, B);
    spe_stage2<<<g2, 256>>>(nidx, out);
}

// round 8
// speedup vs baseline: 2.2161x; 1.0354x over previous
#include <cuda_runtime.h>
#include <cuda_fp16.h>
#include <cstdint>

#define NPTS 32768
#define KNB  16

// Post-BN/ReLU features fp16, layout [b][n][o] (o contiguous). 8.4 MB, L2-resident.
__device__ __half g_Rh[2 * NPTS * 64];

#define SWZ(x) ((x) ^ (((x) >> 3) & 0x70))

__device__ __forceinline__ uint32_t smem_u32(const void* p) {
    uint32_t a;
    asm("{ .reg .u64 t; cvta.to.shared.u64 t, %1; cvt.u32.u64 %0, t; }" : "=r"(a) : "l"(p));
    return a;
}

#define LDSM4(r, addr) \
    asm volatile("ldmatrix.sync.aligned.m8n8.x4.shared.b16 {%0,%1,%2,%3}, [%4];" \
        : "=r"((r)[0]), "=r"((r)[1]), "=r"((r)[2]), "=r"((r)[3]) : "r"(addr))

#define MMA16816(d, a, b0, b1) \
    asm volatile("mma.sync.aligned.m16n8k16.row.col.f32.f16.f16.f32 " \
        "{%0,%1,%2,%3}, {%4,%5,%6,%7}, {%8,%9}, {%0,%1,%2,%3};" \
        : "+f"((d)[0]), "+f"((d)[1]), "+f"((d)[2]), "+f"((d)[3]) \
        : "r"((a)[0]), "r"((a)[1]), "r"((a)[2]), "r"((a)[3]), "r"(b0), "r"(b1))

// ---------------------------------------------------------------------------
// Stage 1 (HMMA): R[b][n][o] = relu( F[64n x 64c] @ Ws[64o x 64c]^T + bias )
// 64-point tile per CTA -> 1024 CTAs for latency hiding on DRAM loads.
// ---------------------------------------------------------------------------
__global__ __launch_bounds__(128) void spe_stage1(
    const float* __restrict__ feat,
    const float* __restrict__ W,
    const float* __restrict__ gamma,
    const float* __restrict__ beta,
    const float* __restrict__ rmean,
    const float* __restrict__ rvar)
{
    __shared__ __align__(128) char sA[64 * 128];   // F tile [n][c] fp16, SW128; reused for output
    __shared__ __align__(128) char sW[64 * 128];   // Ws [o][c] fp16, SW128
    __shared__ float sBias[64];

    const int tid = threadIdx.x, wid = tid >> 5, lane = tid & 31;
    const int b  = blockIdx.y;
    const int n0 = blockIdx.x * 64;

    if (tid < 64) {
        float inv = gamma[tid] * rsqrtf(rvar[tid] + 1e-5f);
        sBias[tid] = beta[tid] - rmean[tid] * inv;
    }

    // Ws[o][c] = W[o][c] * inv[o], fp16, rows of 128B (64 halves)
    #pragma unroll
    for (int e = tid; e < 2048; e += 128) {
        int o = e >> 5, c2 = e & 31;
        float inv = gamma[o] * rsqrtf(rvar[o] + 1e-5f);
        float2 w2 = *(const float2*)&W[o * 64 + c2 * 2];
        __half2 h = __floats2half2_rn(w2.x * inv, w2.y * inv);
        *(uint32_t*)(sW + SWZ(o * 128 + c2 * 4)) = *(uint32_t*)&h;
    }

    // F[n][c] fp16: transpose-convert from feat[b][c][n0..n0+63]
    #pragma unroll
    for (int e = tid; e < 512; e += 128) {
        int c2 = e >> 4, nq = e & 15;   // c-pair, n-quad
        const float* p0 = &feat[((size_t)b * 64 + 2 * c2) * NPTS + n0 + nq * 4];
        float4 f0 = *(const float4*)p0;
        float4 f1 = *(const float4*)(p0 + NPTS);
        __half2 h0 = __floats2half2_rn(f0.x, f1.x);
        __half2 h1 = __floats2half2_rn(f0.y, f1.y);
        __half2 h2 = __floats2half2_rn(f0.z, f1.z);
        __half2 h3 = __floats2half2_rn(f0.w, f1.w);
        int nl = nq * 4;
        *(uint32_t*)(sA + SWZ((nl + 0) * 128 + c2 * 4)) = *(uint32_t*)&h0;
        *(uint32_t*)(sA + SWZ((nl + 1) * 128 + c2 * 4)) = *(uint32_t*)&h1;
        *(uint32_t*)(sA + SWZ((nl + 2) * 128 + c2 * 4)) = *(uint32_t*)&h2;
        *(uint32_t*)(sA + SWZ((nl + 3) * 128 + c2 * 4)) = *(uint32_t*)&h3;
    }
    __syncthreads();

    const uint32_t smA = smem_u32(sA), smW = smem_u32(sW);

    float acc[8][4];
    #pragma unroll
    for (int j = 0; j < 8; j++)
        #pragma unroll
        for (int q = 0; q < 4; q++) acc[j][q] = 0.f;

    int aBase;
    {
        int row_in = (lane & 7) + ((lane >> 3) & 1) * 8;
        int kchunk = ((lane >> 4) & 1) * 16;
        aBase = (wid * 16 + row_in) * 128 + kchunk;
    }
    int bBase[4];
    {
        int row_in = lane & 7;
        int nsel   = (lane >> 4) & 1;
        int kchunk = ((lane >> 3) & 1) * 16;
        #pragma unroll
        for (int jj = 0; jj < 4; jj++)
            bBase[jj] = ((2 * jj + nsel) * 8 + row_in) * 128 + kchunk;
    }

    #pragma unroll
    for (int k = 0; k < 4; k++) {
        uint32_t af[4], bf[4][4];
        LDSM4(af, smA + SWZ(aBase + k * 32));
        #pragma unroll
        for (int jj = 0; jj < 4; jj++)
            LDSM4(bf[jj], smW + SWZ(bBase[jj] + k * 32));
        #pragma unroll
        for (int j = 0; j < 8; j++)
            MMA16816(acc[j], af, bf[j >> 1][(j & 1) * 2], bf[j >> 1][(j & 1) * 2 + 1]);
    }

    __syncthreads();   // done reading sA/sW; reuse sA for output staging

    const int r0 = wid * 16 + (lane >> 2);
    const int cq = lane & 3;
    #pragma unroll
    for (int j = 0; j < 8; j++) {
        float2 bb = *(float2*)&sBias[j * 8 + cq * 2];
        __half2 h01 = __floats2half2_rn(fmaxf(acc[j][0] + bb.x, 0.f),
                                        fmaxf(acc[j][1] + bb.y, 0.f));
        __half2 h23 = __floats2half2_rn(fmaxf(acc[j][2] + bb.x, 0.f),
                                        fmaxf(acc[j][3] + bb.y, 0.f));
        int colb = j * 16 + cq * 4;
        *(uint32_t*)(sA + SWZ(r0 * 128 + colb))       = *(uint32_t*)&h01;
        *(uint32_t*)(sA + SWZ((r0 + 8) * 128 + colb)) = *(uint32_t*)&h23;
    }
    __syncthreads();

    __half* Rb = g_Rh + (((size_t)b * NPTS + n0) << 6);
    #pragma unroll
    for (int i = tid; i < 512; i += 128) {
        int row = i >> 3, seg = i & 7;
        uint4 v = *(uint4*)(sA + SWZ(row * 128 + seg * 16));
        *(uint4*)(Rb + ((size_t)row << 6) + seg * 8) = v;
    }
}

// ---------------------------------------------------------------------------
// Stage 2: out[b][o][n] = R[b][n][o] + sum_k R[b][idx[n][k]][o]
// 8 threads/point, 16B uint4 gathers, fp16 HADD2 group-of-4 trees, fp32 acc.
// Block 256 threads = 32 points.
// ---------------------------------------------------------------------------
__device__ __forceinline__ void gred4(float* a, uint4 v0, uint4 v1, uint4 v2, uint4 v3) {
    #pragma unroll
    for (int j = 0; j < 4; j++) {
        __half2 s = __hadd2(__hadd2(((__half2*)&v0)[j], ((__half2*)&v1)[j]),
                            __hadd2(((__half2*)&v2)[j], ((__half2*)&v3)[j]));
        float2 f = __half22float2(s);
        a[2 * j]     += f.x;
        a[2 * j + 1] += f.y;
    }
}
__device__ __forceinline__ void acc16(float* a, uint4 v) {
    #pragma unroll
    for (int j = 0; j < 4; j++) {
        float2 f = __half22float2(((__half2*)&v)[j]);
        a[2 * j]     += f.x;
        a[2 * j + 1] += f.y;
    }
}

__global__ __launch_bounds__(256) void spe_stage2(
    const int* __restrict__ nidx,
    float* __restrict__ out)
{
    __shared__ float s[32][68];

    const int b   = blockIdx.y;
    const int n0  = blockIdx.x * 32;
    const int tid = threadIdx.x;
    const int p   = tid >> 3;     // point 0..31
    const int g   = tid & 7;      // 16B segment
    const int n   = n0 + p;

    const __half* __restrict__ Rb = g_Rh + ((size_t)b << 21);

    const int4* ip = (const int4*)(nidx + ((size_t)(b * NPTS + n)) * KNB);
    int4 i0 = ip[0], i1 = ip[1], i2 = ip[2], i3 = ip[3];

    float a[8];
    #pragma unroll
    for (int j = 0; j < 8; j++) a[j] = 0.f;

    #define LD16(idx) (((const uint4*)(Rb + ((size_t)(idx) << 6)))[g])
    uint4 A0 = LD16(n);    uint4 A1 = LD16(i0.x); uint4 A2 = LD16(i0.y); uint4 A3 = LD16(i0.z);
    uint4 B0 = LD16(i0.w); uint4 B1 = LD16(i1.x); uint4 B2 = LD16(i1.y); uint4 B3 = LD16(i1.z);
    gred4(a, A0, A1, A2, A3);
    uint4 C0 = LD16(i1.w); uint4 C1 = LD16(i2.x); uint4 C2 = LD16(i2.y); uint4 C3 = LD16(i2.z);
    gred4(a, B0, B1, B2, B3);
    uint4 D0 = LD16(i2.w); uint4 D1 = LD16(i3.x); uint4 D2 = LD16(i3.y); uint4 D3 = LD16(i3.z);
    gred4(a, C0, C1, C2, C3);
    uint4 E0 = LD16(i3.w);
    gred4(a, D0, D1, D2, D3);
    acc16(a, E0);
    #undef LD16

    *(float4*)&s[p][g * 8]     = make_float4(a[0], a[1], a[2], a[3]);
    *(float4*)&s[p][g * 8 + 4] = make_float4(a[4], a[5], a[6], a[7]);
    __syncthreads();

    // coalesced write-out: out[b][o][n0..n0+31]
    const int o = tid & 63;
    const int q = tid >> 6;    // 0..3
    #pragma unroll
    for (int h = 0; h < 2; h++) {
        int qq = q + h * 4;    // 0..7
        float4 r;
        r.x = s[qq * 4 + 0][o];
        r.y = s[qq * 4 + 1][o];
        r.z = s[qq * 4 + 2][o];
        r.w = s[qq * 4 + 3][o];
        *(float4*)&out[((size_t)b * 64 + o) * NPTS + n0 + qq * 4] = r;
    }
}

extern "C" void kernel_launch(void* const* d_in, const int* in_sizes, int n_in,
                              void* d_out, int out_size) {
    const float* feature = (const float*)d_in[0];
    const int*   nidx    = (const int*)d_in[1];
    const float* W       = (const float*)d_in[2];
    const float* gamma   = (const float*)d_in[3];
    const float* beta    = (const float*)d_in[4];
    const float* rmean   = (const float*)d_in[5];
    const float* rvar    = (const float*)d_in[6];
    float* out = (float*)d_out;

    const int B = in_sizes[0] / (64 * NPTS);   // = 2

    dim3 g1(NPTS / 64, B);
    spe_stage1<<<g1, 128>>>(feature, W, gamma, beta, rmean, rvar);

    dim3 g2(NPTS / 32, B);
    spe_stage2<<<g2, 256>>>(nidx, out);
}